// round 7
// baseline (speedup 1.0000x reference)
#include <cuda_runtime.h>
#include <utility>

#define RB 20
#define RA 19
#define MUL 128
#define NC 128
#define NBATCH 1024
#define D1 9
#define DZ 25
#define ZSTRIDE 28     // padded stride for 25-float z rows (112B, 16B aligned)
#define XYSTRIDE 20    // [xd1..8][yd1..8][xd0][yd0][pad][pad] (80B, 16B aligned)
#define TILE_N 2

// ===================== compile-time selection rules =====================
__host__ __device__ constexpr int lof(int d) {
    return (d < 1) ? 0 : (d < 4) ? 1 : (d < 9) ? 2 : (d < 16) ? 3 : 4;
}
__host__ __device__ constexpr bool gaunt_nz(int i, int j, int d) {
    const int l1 = lof(i), m1 = i - l1 * l1 - l1;
    const int l2 = lof(j), m2 = j - l2 * l2 - l2;
    const int L  = lof(d), M  = d - L * L - L;
    if ((l1 + l2 + L) & 1) return false;
    const int lo = (l1 > l2) ? (l1 - l2) : (l2 - l1);
    if (L < lo || L > l1 + l2) return false;
    const int f1 = m1 < 0 ? -m1 : m1;
    const int f2 = m2 < 0 ? -m2 : m2;
    const int F  = M  < 0 ? -M  : M;
    const int fd = (f1 > f2) ? (f1 - f2) : (f2 - f1);
    if (!(F == f1 + f2 || F == fd)) return false;
    if (((m1 < 0) + (m2 < 0) + (M < 0)) & 1) return false;
    return true;
}

// ===================== compile-time Gaunt table =====================
namespace cgaunt {

constexpr double PI = 3.14159265358979323846;

constexpr double csqrt(double x) {
    double r = (x > 1.0) ? x : 1.0;
    for (int i = 0; i < 80; ++i) r = 0.5 * (r + x / r);
    return r;
}
constexpr double redang(double x) {
    while (x >  PI) x -= 2.0 * PI;
    while (x < -PI) x += 2.0 * PI;
    return x;
}
constexpr double ccos(double x) {
    x = redang(x);
    double x2 = x * x, t = 1.0, s = 1.0;
    for (int k = 1; k <= 22; ++k) { t *= -x2 / ((2.0 * k - 1.0) * (2.0 * k)); s += t; }
    return s;
}
constexpr double csin(double x) {
    x = redang(x);
    double x2 = x * x, t = x, s = x;
    for (int k = 1; k <= 22; ++k) { t *= -x2 / ((2.0 * k) * (2.0 * k + 1.0)); s += t; }
    return s;
}
constexpr double cfact(int k) { double f = 1.0; for (int v = 2; v <= k; ++v) f *= v; return f; }

constexpr double alegP(int l, int m, double x) {
    double pmm = 1.0;
    if (m > 0) {
        double df = 1.0;
        for (int k = 1; k < 2 * m; k += 2) df *= (double)k;
        double somx2 = csqrt(1.0 - x * x);
        double s = 1.0;
        for (int k = 0; k < m; ++k) s *= somx2;
        pmm = ((m & 1) ? -1.0 : 1.0) * df * s;
    }
    if (l == m) return pmm;
    double pmmp1 = x * (2.0 * m + 1.0) * pmm;
    if (l == m + 1) return pmmp1;
    for (int ll = m + 2; ll <= l; ++ll) {
        double p = ((2.0 * ll - 1.0) * x * pmmp1 - (ll + m - 1.0) * pmm) / (double)(ll - m);
        pmm = pmmp1; pmmp1 = p;
    }
    return pmmp1;
}

struct GTab { double g[81][DZ]; };

constexpr GTab make_gaunt() {
    GTab T{};
    double ct[RB] = {}, qw[RB] = {};
    for (int i = 0; i < RB; ++i) {
        double xv = ccos(PI * (i + 0.75) / (RB + 0.5));
        double dp = 0.0;
        for (int it = 0; it < 60; ++it) {
            double p0 = 1.0, p1 = xv;
            for (int k = 2; k <= RB; ++k) {
                double p = ((2.0 * k - 1.0) * xv * p1 - (k - 1.0) * p0) / (double)k;
                p0 = p1; p1 = p;
            }
            dp = RB * (xv * p1 - p0) / (xv * xv - 1.0);
            xv -= p1 / dp;
        }
        {
            double p0 = 1.0, p1 = xv;
            for (int k = 2; k <= RB; ++k) {
                double p = ((2.0 * k - 1.0) * xv * p1 - (k - 1.0) * p0) / (double)k;
                p0 = p1; p1 = p;
            }
            dp = RB * (xv * p1 - p0) / (xv * xv - 1.0);
        }
        ct[i] = xv;
        qw[i] = 2.0 / ((1.0 - xv * xv) * dp * dp);
    }
    double Pn[DZ][RB] = {}, U[DZ][RA] = {};
    for (int d = 0; d < DZ; ++d) {
        int l = lof(d);
        int m = d - l * l - l;
        int am = m < 0 ? -m : m;
        double nlm = csqrt((2.0 * l + 1.0) / (4.0 * PI) * cfact(l - am) / cfact(l + am));
        for (int b = 0; b < RB; ++b) Pn[d][b] = nlm * alegP(l, am, ct[b]);
        for (int a = 0; a < RA; ++a) {
            double al = 2.0 * PI * (double)a / (double)RA;
            U[d][a] = (m == 0) ? 1.0
                    : (m > 0 ? csqrt(2.0) * ccos((double)m * al)
                             : csqrt(2.0) * csin((double)am * al));
        }
    }
    const double scale = (2.0 * PI / (double)RA) / (double)MUL / csqrt((double)NC);
    for (int i = 0; i < 9; ++i)
        for (int j = 0; j < 9; ++j)
            for (int d = 0; d < DZ; ++d) {
                if (!gaunt_nz(i, j, d)) { T.g[i * 9 + j][d] = 0.0; continue; }
                double angs = 0.0;
                for (int a = 0; a < RA; ++a) angs += U[i][a] * U[j][a] * U[d][a];
                double bets = 0.0;
                for (int b = 0; b < RB; ++b) bets += qw[b] * Pn[i][b] * Pn[j][b] * Pn[d][b];
                T.g[i * 9 + j][d] = angs * bets * scale;
            }
    return T;
}

constexpr GTab GG = make_gaunt();

} // namespace cgaunt

// ===================== static_for =====================
template <typename F, int... Is>
__device__ __forceinline__ void sfor_impl(F&& f, std::integer_sequence<int, Is...>) {
    (f(std::integral_constant<int, Is>{}), ...);
}
template <int N, typename F>
__device__ __forceinline__ void sfor(F&& f) {
    sfor_impl(static_cast<F&&>(f), std::make_integer_sequence<int, N>{});
}

// ===================== packed f32x2 helpers =====================
__device__ __forceinline__ unsigned long long pk2(float lo, float hi) {
    unsigned long long r;
    asm("mov.b64 %0, {%1, %2};" : "=l"(r) : "f"(lo), "f"(hi));
    return r;
}
__device__ __forceinline__ void ffma2(unsigned long long& d,
                                      unsigned long long a, unsigned long long b) {
    asm("fma.rn.f32x2 %0, %1, %2, %0;" : "+l"(d) : "l"(a), "l"(b));
}
__device__ __forceinline__ void unpk2(unsigned long long v, float& lo, float& hi) {
    asm("mov.b64 {%0, %1}, %2;" : "=f"(lo), "=f"(hi) : "l"(v));
}

// ===================== pre-packed weights (device scratch) =====================
__device__ float4 WA[MUL * NC];    // (wx_l0, wx_l1, wx_l2, wy_l0) at [m*128+c]
__device__ float2 WB[MUL * NC];    // (wy_l1, wy_l2)
__device__ float4 WZ4[NC * NC];    // (wz_l0..wz_l3) at [cc*128+c]
__device__ float  WZ1[NC * NC];    // wz_l4

__global__ void pack_weights(const float* __restrict__ wx,
                             const float* __restrict__ wy,
                             const float* __restrict__ wz) {
    int idx = blockIdx.x * 256 + threadIdx.x;   // 0..16383
    WA[idx] = make_float4(wx[idx], wx[16384 + idx], wx[32768 + idx], wy[idx]);
    WB[idx] = make_float2(wy[16384 + idx], wy[32768 + idx]);
    WZ4[idx] = make_float4(wz[idx], wz[16384 + idx], wz[32768 + idx], wz[49152 + idx]);
    WZ1[idx] = wz[65536 + idx];
}

// ===================== stage helpers =====================
struct S1Acc {
    unsigned long long Ax[4], Ay[4];
    float sx, sy;
    __device__ __forceinline__ void init() {
        #pragma unroll
        for (int k = 0; k < 4; ++k) { Ax[k] = Ay[k] = 0ULL; }
        sx = sy = 0.0f;
    }
    __device__ __forceinline__ void step(const float* __restrict__ row,
                                         unsigned long long pbb, unsigned long long pbc,
                                         unsigned long long pcc, unsigned long long pdd,
                                         unsigned long long pde, unsigned long long pee,
                                         float wxa, float wya) {
        float4 xv0 = *(const float4*)(row);       // xd1..xd4
        float4 xv1 = *(const float4*)(row + 4);   // xd5..xd8
        float4 yv0 = *(const float4*)(row + 8);   // yd1..yd4
        float4 yv1 = *(const float4*)(row + 12);  // yd5..yd8
        float2 d0  = *(const float2*)(row + 16);  // xd0, yd0
        ffma2(Ax[0], pk2(xv0.x, xv0.y), pbb);
        ffma2(Ax[1], pk2(xv0.z, xv0.w), pbc);
        ffma2(Ax[2], pk2(xv1.x, xv1.y), pcc);
        ffma2(Ax[3], pk2(xv1.z, xv1.w), pcc);
        sx += d0.x * wxa;
        ffma2(Ay[0], pk2(yv0.x, yv0.y), pdd);
        ffma2(Ay[1], pk2(yv0.z, yv0.w), pde);
        ffma2(Ay[2], pk2(yv1.x, yv1.y), pee);
        ffma2(Ay[3], pk2(yv1.z, yv1.w), pee);
        sy += d0.y * wya;
    }
    __device__ __forceinline__ void unpack(float* xc, float* yc) {
        xc[0] = sx; yc[0] = sy;
        #pragma unroll
        for (int k = 0; k < 4; ++k) {
            unpk2(Ax[k], xc[2 * k + 1], xc[2 * k + 2]);
            unpk2(Ay[k], yc[2 * k + 1], yc[2 * k + 2]);
        }
    }
};

__device__ __forceinline__ void gaunt_contract_ct(const float* __restrict__ xc,
                                                  const float* __restrict__ yc,
                                                  float* __restrict__ z) {
    #pragma unroll
    for (int d = 0; d < DZ; ++d) z[d] = 0.0f;
    sfor<9>([&](auto I) {
        constexpr int i = decltype(I)::value;
        sfor<9>([&](auto J) {
            constexpr int j = decltype(J)::value;
            float p = xc[i] * yc[j];
            sfor<DZ>([&](auto Dd) {
                constexpr int d = decltype(Dd)::value;
                if constexpr (gaunt_nz(i, j, d)) {
                    constexpr float gv = (float)cgaunt::GG.g[i * 9 + j][d];
                    z[d] = fmaf(p, gv, z[d]);
                }
            });
        });
    });
}

struct S3Acc {
    unsigned long long a[12];
    float as;
    __device__ __forceinline__ void init() {
        #pragma unroll
        for (int k = 0; k < 12; ++k) a[k] = 0ULL;
        as = 0.0f;
    }
    __device__ __forceinline__ void step(const float* __restrict__ zp,
                                         unsigned long long p01, unsigned long long p11,
                                         unsigned long long p22, unsigned long long p23,
                                         unsigned long long p33, unsigned long long p44,
                                         float w4) {
        float4 q0 = *(const float4*)(zp);
        float4 q1 = *(const float4*)(zp + 4);
        float4 q2 = *(const float4*)(zp + 8);
        float4 q3 = *(const float4*)(zp + 12);
        float4 q4 = *(const float4*)(zp + 16);
        float4 q5 = *(const float4*)(zp + 20);
        float  zl = zp[24];
        ffma2(a[0],  pk2(q0.x, q0.y), p01);
        ffma2(a[1],  pk2(q0.z, q0.w), p11);
        ffma2(a[2],  pk2(q1.x, q1.y), p22);
        ffma2(a[3],  pk2(q1.z, q1.w), p22);
        ffma2(a[4],  pk2(q2.x, q2.y), p23);
        ffma2(a[5],  pk2(q2.z, q2.w), p33);
        ffma2(a[6],  pk2(q3.x, q3.y), p33);
        ffma2(a[7],  pk2(q3.z, q3.w), p33);
        ffma2(a[8],  pk2(q4.x, q4.y), p44);
        ffma2(a[9],  pk2(q4.z, q4.w), p44);
        ffma2(a[10], pk2(q5.x, q5.y), p44);
        ffma2(a[11], pk2(q5.z, q5.w), p44);
        as += zl * w4;
    }
    // NOTE: output rows are only 4-byte aligned ((n*NC+c)*25*4 = 100B multiples),
    // so stores MUST be scalar.
    __device__ __forceinline__ void store(float* __restrict__ og) {
        #pragma unroll
        for (int k = 0; k < 12; ++k) {
            float lo, hi;
            unpk2(a[k], lo, hi);
            og[2 * k] = lo;
            og[2 * k + 1] = hi;
        }
        og[24] = as;
    }
};

// ===================== main fused kernel: 2 nodes per block =====================
__global__ void __launch_bounds__(128, 4)
gaunt_main_kernel(const float* __restrict__ x, const float* __restrict__ y,
                  float* __restrict__ out) {
    __shared__ __align__(16) float pool[TILE_N * NC * ZSTRIDE];  // 28672 B

    const int c = threadIdx.x;
    const int n0 = blockIdx.x * TILE_N;

    float* xy0 = pool;                        // 128 rows * 20
    float* xy1 = pool + NC * XYSTRIDE;        // second node

    // ---- cooperative stage-in ----
    {
        const float* xg0 = x + (size_t)n0 * MUL * D1;
        const float* yg0 = y + (size_t)n0 * MUL * D1;
        const float* xg1 = xg0 + MUL * D1;
        const float* yg1 = yg0 + MUL * D1;
        #pragma unroll
        for (int it = 0; it < 9; ++it) {
            int idx = c + it * 128;
            int m = idx / 9, dd = idx - m * 9;
            int kx = (dd == 0) ? 16 : (dd - 1);
            int ky = (dd == 0) ? 17 : (7 + dd);
            xy0[m * XYSTRIDE + kx] = xg0[idx];
            xy0[m * XYSTRIDE + ky] = yg0[idx];
            xy1[m * XYSTRIDE + kx] = xg1[idx];
            xy1[m * XYSTRIDE + ky] = yg1[idx];
        }
    }
    __syncthreads();

    // ---- stage 1: shared weight loads feed both nodes ----
    S1Acc A0, A1;
    A0.init(); A1.init();

    #pragma unroll 2
    for (int m = 0; m < MUL; ++m) {
        float4 wa = WA[m * NC + c];
        float2 wb = WB[m * NC + c];
        unsigned long long pbb = pk2(wa.y, wa.y);
        unsigned long long pbc = pk2(wa.y, wa.z);
        unsigned long long pcc = pk2(wa.z, wa.z);
        unsigned long long pdd = pk2(wb.x, wb.x);
        unsigned long long pde = pk2(wb.x, wb.y);
        unsigned long long pee = pk2(wb.y, wb.y);
        A0.step(&xy0[m * XYSTRIDE], pbb, pbc, pcc, pdd, pde, pee, wa.x, wa.w);
        A1.step(&xy1[m * XYSTRIDE], pbb, pbc, pcc, pdd, pde, pee, wa.x, wa.w);
    }

    float xc[9], yc[9], z0[DZ], z1[DZ];
    A0.unpack(xc, yc);
    gaunt_contract_ct(xc, yc, z0);
    A1.unpack(xc, yc);
    gaunt_contract_ct(xc, yc, z1);

    __syncthreads();   // all warps done reading xy before z overwrites pool

    float* zs0 = pool;
    float* zs1 = pool + NC * ZSTRIDE;
    {
        float* zr = &zs0[c * ZSTRIDE];   // c*112B -> 16B aligned
        *(float4*)(zr)      = make_float4(z0[0],  z0[1],  z0[2],  z0[3]);
        *(float4*)(zr + 4)  = make_float4(z0[4],  z0[5],  z0[6],  z0[7]);
        *(float4*)(zr + 8)  = make_float4(z0[8],  z0[9],  z0[10], z0[11]);
        *(float4*)(zr + 12) = make_float4(z0[12], z0[13], z0[14], z0[15]);
        *(float4*)(zr + 16) = make_float4(z0[16], z0[17], z0[18], z0[19]);
        *(float4*)(zr + 20) = make_float4(z0[20], z0[21], z0[22], z0[23]);
        zr[24] = z0[24];
        zr = &zs1[c * ZSTRIDE];
        *(float4*)(zr)      = make_float4(z1[0],  z1[1],  z1[2],  z1[3]);
        *(float4*)(zr + 4)  = make_float4(z1[4],  z1[5],  z1[6],  z1[7]);
        *(float4*)(zr + 8)  = make_float4(z1[8],  z1[9],  z1[10], z1[11]);
        *(float4*)(zr + 12) = make_float4(z1[12], z1[13], z1[14], z1[15]);
        *(float4*)(zr + 16) = make_float4(z1[16], z1[17], z1[18], z1[19]);
        *(float4*)(zr + 20) = make_float4(z1[20], z1[21], z1[22], z1[23]);
        zr[24] = z1[24];
    }
    __syncthreads();

    // ---- stage 3: shared weight loads feed both nodes ----
    S3Acc B0, B1;
    B0.init(); B1.init();

    #pragma unroll 2
    for (int cc = 0; cc < NC; ++cc) {
        float4 wv = WZ4[cc * NC + c];
        float  w4 = WZ1[cc * NC + c];
        unsigned long long p01 = pk2(wv.x, wv.y);
        unsigned long long p11 = pk2(wv.y, wv.y);
        unsigned long long p22 = pk2(wv.z, wv.z);
        unsigned long long p23 = pk2(wv.z, wv.w);
        unsigned long long p33 = pk2(wv.w, wv.w);
        unsigned long long p44 = pk2(w4, w4);
        B0.step(&zs0[cc * ZSTRIDE], p01, p11, p22, p23, p33, p44, w4);
        B1.step(&zs1[cc * ZSTRIDE], p01, p11, p22, p23, p33, p44, w4);
    }

    // ---- write out (scalar stores: 100B row alignment) ----
    B0.store(out + ((size_t)n0 * NC + c) * DZ);
    B1.store(out + ((size_t)(n0 + 1) * NC + c) * DZ);
}

extern "C" void kernel_launch(void* const* d_in, const int* in_sizes, int n_in,
                              void* d_out, int out_size) {
    const float* x  = (const float*)d_in[0];
    const float* y  = (const float*)d_in[1];
    const float* wx = (const float*)d_in[2];
    const float* wy = (const float*)d_in[3];
    const float* wz = (const float*)d_in[4];
    float* out = (float*)d_out;

    pack_weights<<<64, 256>>>(wx, wy, wz);
    gaunt_main_kernel<<<NBATCH / TILE_N, 128>>>(x, y, out);
}

// round 8
// speedup vs baseline: 1.2887x; 1.2887x over previous
#include <cuda_runtime.h>
#include <utility>

#define RB 20
#define RA 19
#define MUL 128
#define NC 128
#define NBATCH 1024
#define D1 9
#define DZ 25
#define ZSTRIDE 28     // padded stride for 25-float z rows (112B, 16B aligned)
#define XYSTRIDE 20    // [xd1..8][yd1..8][xd0][yd0][pad][pad] (80B, 16B aligned)

// ===================== compile-time selection rules =====================
__host__ __device__ constexpr int lof(int d) {
    return (d < 1) ? 0 : (d < 4) ? 1 : (d < 9) ? 2 : (d < 16) ? 3 : 4;
}
__host__ __device__ constexpr bool gaunt_nz(int i, int j, int d) {
    const int l1 = lof(i), m1 = i - l1 * l1 - l1;
    const int l2 = lof(j), m2 = j - l2 * l2 - l2;
    const int L  = lof(d), M  = d - L * L - L;
    if ((l1 + l2 + L) & 1) return false;
    const int lo = (l1 > l2) ? (l1 - l2) : (l2 - l1);
    if (L < lo || L > l1 + l2) return false;
    const int f1 = m1 < 0 ? -m1 : m1;
    const int f2 = m2 < 0 ? -m2 : m2;
    const int F  = M  < 0 ? -M  : M;
    const int fd = (f1 > f2) ? (f1 - f2) : (f2 - f1);
    if (!(F == f1 + f2 || F == fd)) return false;
    if (((m1 < 0) + (m2 < 0) + (M < 0)) & 1) return false;
    return true;
}

// ===================== compile-time Gaunt table =====================
namespace cgaunt {

constexpr double PI = 3.14159265358979323846;

constexpr double csqrt(double x) {
    double r = (x > 1.0) ? x : 1.0;
    for (int i = 0; i < 80; ++i) r = 0.5 * (r + x / r);
    return r;
}
constexpr double redang(double x) {
    while (x >  PI) x -= 2.0 * PI;
    while (x < -PI) x += 2.0 * PI;
    return x;
}
constexpr double ccos(double x) {
    x = redang(x);
    double x2 = x * x, t = 1.0, s = 1.0;
    for (int k = 1; k <= 22; ++k) { t *= -x2 / ((2.0 * k - 1.0) * (2.0 * k)); s += t; }
    return s;
}
constexpr double csin(double x) {
    x = redang(x);
    double x2 = x * x, t = x, s = x;
    for (int k = 1; k <= 22; ++k) { t *= -x2 / ((2.0 * k) * (2.0 * k + 1.0)); s += t; }
    return s;
}
constexpr double cfact(int k) { double f = 1.0; for (int v = 2; v <= k; ++v) f *= v; return f; }

constexpr double alegP(int l, int m, double x) {
    double pmm = 1.0;
    if (m > 0) {
        double df = 1.0;
        for (int k = 1; k < 2 * m; k += 2) df *= (double)k;
        double somx2 = csqrt(1.0 - x * x);
        double s = 1.0;
        for (int k = 0; k < m; ++k) s *= somx2;
        pmm = ((m & 1) ? -1.0 : 1.0) * df * s;
    }
    if (l == m) return pmm;
    double pmmp1 = x * (2.0 * m + 1.0) * pmm;
    if (l == m + 1) return pmmp1;
    for (int ll = m + 2; ll <= l; ++ll) {
        double p = ((2.0 * ll - 1.0) * x * pmmp1 - (ll + m - 1.0) * pmm) / (double)(ll - m);
        pmm = pmmp1; pmmp1 = p;
    }
    return pmmp1;
}

struct GTab { double g[81][DZ]; };

constexpr GTab make_gaunt() {
    GTab T{};
    double ct[RB] = {}, qw[RB] = {};
    for (int i = 0; i < RB; ++i) {
        double xv = ccos(PI * (i + 0.75) / (RB + 0.5));
        double dp = 0.0;
        for (int it = 0; it < 60; ++it) {
            double p0 = 1.0, p1 = xv;
            for (int k = 2; k <= RB; ++k) {
                double p = ((2.0 * k - 1.0) * xv * p1 - (k - 1.0) * p0) / (double)k;
                p0 = p1; p1 = p;
            }
            dp = RB * (xv * p1 - p0) / (xv * xv - 1.0);
            xv -= p1 / dp;
        }
        {
            double p0 = 1.0, p1 = xv;
            for (int k = 2; k <= RB; ++k) {
                double p = ((2.0 * k - 1.0) * xv * p1 - (k - 1.0) * p0) / (double)k;
                p0 = p1; p1 = p;
            }
            dp = RB * (xv * p1 - p0) / (xv * xv - 1.0);
        }
        ct[i] = xv;
        qw[i] = 2.0 / ((1.0 - xv * xv) * dp * dp);
    }
    double Pn[DZ][RB] = {}, U[DZ][RA] = {};
    for (int d = 0; d < DZ; ++d) {
        int l = lof(d);
        int m = d - l * l - l;
        int am = m < 0 ? -m : m;
        double nlm = csqrt((2.0 * l + 1.0) / (4.0 * PI) * cfact(l - am) / cfact(l + am));
        for (int b = 0; b < RB; ++b) Pn[d][b] = nlm * alegP(l, am, ct[b]);
        for (int a = 0; a < RA; ++a) {
            double al = 2.0 * PI * (double)a / (double)RA;
            U[d][a] = (m == 0) ? 1.0
                    : (m > 0 ? csqrt(2.0) * ccos((double)m * al)
                             : csqrt(2.0) * csin((double)am * al));
        }
    }
    const double scale = (2.0 * PI / (double)RA) / (double)MUL / csqrt((double)NC);
    for (int i = 0; i < 9; ++i)
        for (int j = 0; j < 9; ++j)
            for (int d = 0; d < DZ; ++d) {
                if (!gaunt_nz(i, j, d)) { T.g[i * 9 + j][d] = 0.0; continue; }
                double angs = 0.0;
                for (int a = 0; a < RA; ++a) angs += U[i][a] * U[j][a] * U[d][a];
                double bets = 0.0;
                for (int b = 0; b < RB; ++b) bets += qw[b] * Pn[i][b] * Pn[j][b] * Pn[d][b];
                T.g[i * 9 + j][d] = angs * bets * scale;
            }
    return T;
}

constexpr GTab GG = make_gaunt();

} // namespace cgaunt

// ===================== static_for =====================
template <typename F, int... Is>
__device__ __forceinline__ void sfor_impl(F&& f, std::integer_sequence<int, Is...>) {
    (f(std::integral_constant<int, Is>{}), ...);
}
template <int N, typename F>
__device__ __forceinline__ void sfor(F&& f) {
    sfor_impl(static_cast<F&&>(f), std::make_integer_sequence<int, N>{});
}

// ===================== packed f32x2 helpers =====================
__device__ __forceinline__ unsigned long long pk2(float lo, float hi) {
    unsigned long long r;
    asm("mov.b64 %0, {%1, %2};" : "=l"(r) : "f"(lo), "f"(hi));
    return r;
}
__device__ __forceinline__ void ffma2(unsigned long long& d,
                                      unsigned long long a, unsigned long long b) {
    asm("fma.rn.f32x2 %0, %1, %2, %0;" : "+l"(d) : "l"(a), "l"(b));
}
__device__ __forceinline__ void unpk2(unsigned long long v, float& lo, float& hi) {
    asm("mov.b64 {%0, %1}, %2;" : "=f"(lo), "=f"(hi) : "l"(v));
}

// ===================== pre-packed weights (device scratch) =====================
__device__ float4 WA[MUL * NC];    // (wx_l0, wx_l1, wx_l2, wy_l0) at [m*128+c]
__device__ float2 WB[MUL * NC];    // (wy_l1, wy_l2)
__device__ float4 WZ4[NC * NC];    // (wz_l0..wz_l3) at [cc*128+c]
__device__ float  WZ1[NC * NC];    // wz_l4

__global__ void pack_weights(const float* __restrict__ wx,
                             const float* __restrict__ wy,
                             const float* __restrict__ wz) {
    int idx = blockIdx.x * 256 + threadIdx.x;   // 0..16383
    WA[idx] = make_float4(wx[idx], wx[16384 + idx], wx[32768 + idx], wy[idx]);
    WB[idx] = make_float2(wy[16384 + idx], wy[32768 + idx]);
    WZ4[idx] = make_float4(wz[idx], wz[16384 + idx], wz[32768 + idx], wz[49152 + idx]);
    WZ1[idx] = wz[65536 + idx];
}

// ===================== sparse Gaunt contraction (compile-time coeffs) ========
__device__ __forceinline__ void gaunt_contract_ct(const float* __restrict__ xc,
                                                  const float* __restrict__ yc,
                                                  float* __restrict__ z) {
    #pragma unroll
    for (int d = 0; d < DZ; ++d) z[d] = 0.0f;
    sfor<9>([&](auto I) {
        constexpr int i = decltype(I)::value;
        sfor<9>([&](auto J) {
            constexpr int j = decltype(J)::value;
            float p = xc[i] * yc[j];
            sfor<DZ>([&](auto Dd) {
                constexpr int d = decltype(Dd)::value;
                if constexpr (gaunt_nz(i, j, d)) {
                    constexpr float gv = (float)cgaunt::GG.g[i * 9 + j][d];
                    z[d] = fmaf(p, gv, z[d]);
                }
            });
        });
    });
}

// ===================== main fused kernel: 1 node per block =====================
#define S1C 4   // stage-1 pipeline chunk (m per group)
#define S3C 4   // stage-3 pipeline chunk (cc per group)

__global__ void __launch_bounds__(128, 5)
gaunt_main_kernel(const float* __restrict__ x, const float* __restrict__ y,
                  float* __restrict__ out) {
    __shared__ __align__(16) float pool[NC * ZSTRIDE];   // 14336 B

    const int c = threadIdx.x;
    const int n = blockIdx.x;

    // ---- cooperative stage-in: xy row m = [xd1..8][yd1..8][xd0][yd0][pad2] ----
    {
        const float* xg = x + (size_t)n * MUL * D1;
        const float* yg = y + (size_t)n * MUL * D1;
        #pragma unroll
        for (int it = 0; it < 9; ++it) {
            int idx = c + it * 128;
            int m = idx / 9, dd = idx - m * 9;
            int kx = (dd == 0) ? 16 : (dd - 1);
            int ky = (dd == 0) ? 17 : (7 + dd);
            pool[m * XYSTRIDE + kx] = xg[idx];
            pool[m * XYSTRIDE + ky] = yg[idx];
        }
    }
    __syncthreads();

    // ---- stage 1: per-l linear in, software-pipelined weight loads ----
    unsigned long long Ax[4], Ay[4];
    float sx = 0.0f, sy = 0.0f;
    #pragma unroll
    for (int k = 0; k < 4; ++k) { Ax[k] = Ay[k] = 0ULL; }

    float4 wa[2][S1C];
    float2 wb[2][S1C];
    #pragma unroll
    for (int k = 0; k < S1C; ++k) {
        wa[0][k] = WA[k * NC + c];
        wb[0][k] = WB[k * NC + c];
    }

    #pragma unroll
    for (int g = 0; g < MUL / S1C; ++g) {
        const int cur = g & 1, nxt = cur ^ 1;
        if (g < MUL / S1C - 1) {
            #pragma unroll
            for (int k = 0; k < S1C; ++k) {
                int m = (g + 1) * S1C + k;
                wa[nxt][k] = WA[m * NC + c];
                wb[nxt][k] = WB[m * NC + c];
            }
        }
        #pragma unroll
        for (int k = 0; k < S1C; ++k) {
            const int m = g * S1C + k;
            const float4 w4 = wa[cur][k];
            const float2 w2 = wb[cur][k];
            const float* row = &pool[m * XYSTRIDE];
            float4 xv0 = *(const float4*)(row);       // xd1..xd4
            float4 xv1 = *(const float4*)(row + 4);   // xd5..xd8
            float4 yv0 = *(const float4*)(row + 8);   // yd1..yd4
            float4 yv1 = *(const float4*)(row + 12);  // yd5..yd8
            float2 d0  = *(const float2*)(row + 16);  // xd0, yd0
            ffma2(Ax[0], pk2(xv0.x, xv0.y), pk2(w4.y, w4.y));
            ffma2(Ax[1], pk2(xv0.z, xv0.w), pk2(w4.y, w4.z));
            ffma2(Ax[2], pk2(xv1.x, xv1.y), pk2(w4.z, w4.z));
            ffma2(Ax[3], pk2(xv1.z, xv1.w), pk2(w4.z, w4.z));
            sx += d0.x * w4.x;
            ffma2(Ay[0], pk2(yv0.x, yv0.y), pk2(w2.x, w2.x));
            ffma2(Ay[1], pk2(yv0.z, yv0.w), pk2(w2.x, w2.y));
            ffma2(Ay[2], pk2(yv1.x, yv1.y), pk2(w2.y, w2.y));
            ffma2(Ay[3], pk2(yv1.z, yv1.w), pk2(w2.y, w2.y));
            sy += d0.y * w2.x * 0.0f + d0.y * w4.w;   // wy_l0 lives in wa.w
        }
    }

    float xc[9], yc[9];
    xc[0] = sx; yc[0] = sy;
    #pragma unroll
    for (int k = 0; k < 4; ++k) {
        unpk2(Ax[k], xc[2 * k + 1], xc[2 * k + 2]);
        unpk2(Ay[k], yc[2 * k + 1], yc[2 * k + 2]);
    }

    // ---- prefetch first stage-3 weight group BEFORE the barrier ----
    float4 wz4b[2][S3C];
    float  wz1b[2][S3C];
    #pragma unroll
    for (int k = 0; k < S3C; ++k) {
        wz4b[0][k] = WZ4[k * NC + c];
        wz1b[0][k] = WZ1[k * NC + c];
    }

    // ---- stage 2: sparse Gaunt contraction (registers + immediates only) ----
    float z[DZ];
    gaunt_contract_ct(xc, yc, z);

    __syncthreads();   // all warps done reading xy before z overwrites pool

    {
        float* zr = &pool[c * ZSTRIDE];  // c*112B -> 16B aligned
        *(float4*)(zr)      = make_float4(z[0],  z[1],  z[2],  z[3]);
        *(float4*)(zr + 4)  = make_float4(z[4],  z[5],  z[6],  z[7]);
        *(float4*)(zr + 8)  = make_float4(z[8],  z[9],  z[10], z[11]);
        *(float4*)(zr + 12) = make_float4(z[12], z[13], z[14], z[15]);
        *(float4*)(zr + 16) = make_float4(z[16], z[17], z[18], z[19]);
        *(float4*)(zr + 20) = make_float4(z[20], z[21], z[22], z[23]);
        zr[24] = z[24];
    }
    __syncthreads();

    // ---- stage 3: per-l channel mixing, software-pipelined weight loads ----
    unsigned long long a[12];
    float as = 0.0f;
    #pragma unroll
    for (int k = 0; k < 12; ++k) a[k] = 0ULL;

    #pragma unroll
    for (int g = 0; g < NC / S3C; ++g) {
        const int cur = g & 1, nxt = cur ^ 1;
        if (g < NC / S3C - 1) {
            #pragma unroll
            for (int k = 0; k < S3C; ++k) {
                int cc = (g + 1) * S3C + k;
                wz4b[nxt][k] = WZ4[cc * NC + c];
                wz1b[nxt][k] = WZ1[cc * NC + c];
            }
        }
        #pragma unroll
        for (int k = 0; k < S3C; ++k) {
            const int cc = g * S3C + k;
            const float4 wv = wz4b[cur][k];
            const float  w4 = wz1b[cur][k];
            const float* zp = &pool[cc * ZSTRIDE];
            float4 q0 = *(const float4*)(zp);
            float4 q1 = *(const float4*)(zp + 4);
            float4 q2 = *(const float4*)(zp + 8);
            float4 q3 = *(const float4*)(zp + 12);
            float4 q4 = *(const float4*)(zp + 16);
            float4 q5 = *(const float4*)(zp + 20);
            float  zl = zp[24];
            ffma2(a[0],  pk2(q0.x, q0.y), pk2(wv.x, wv.y));
            ffma2(a[1],  pk2(q0.z, q0.w), pk2(wv.y, wv.y));
            ffma2(a[2],  pk2(q1.x, q1.y), pk2(wv.z, wv.z));
            ffma2(a[3],  pk2(q1.z, q1.w), pk2(wv.z, wv.z));
            ffma2(a[4],  pk2(q2.x, q2.y), pk2(wv.z, wv.w));
            ffma2(a[5],  pk2(q2.z, q2.w), pk2(wv.w, wv.w));
            ffma2(a[6],  pk2(q3.x, q3.y), pk2(wv.w, wv.w));
            ffma2(a[7],  pk2(q3.z, q3.w), pk2(wv.w, wv.w));
            ffma2(a[8],  pk2(q4.x, q4.y), pk2(w4, w4));
            ffma2(a[9],  pk2(q4.z, q4.w), pk2(w4, w4));
            ffma2(a[10], pk2(q5.x, q5.y), pk2(w4, w4));
            ffma2(a[11], pk2(q5.z, q5.w), pk2(w4, w4));
            as += zl * w4;
        }
    }

    // ---- write out (scalar stores: output rows are 100B-aligned only) ----
    float* og = out + ((size_t)n * NC + c) * DZ;
    #pragma unroll
    for (int k = 0; k < 12; ++k) {
        float lo, hi;
        unpk2(a[k], lo, hi);
        og[2 * k] = lo;
        og[2 * k + 1] = hi;
    }
    og[24] = as;
}

extern "C" void kernel_launch(void* const* d_in, const int* in_sizes, int n_in,
                              void* d_out, int out_size) {
    const float* x  = (const float*)d_in[0];
    const float* y  = (const float*)d_in[1];
    const float* wx = (const float*)d_in[2];
    const float* wy = (const float*)d_in[3];
    const float* wz = (const float*)d_in[4];
    float* out = (float*)d_out;

    pack_weights<<<64, 256>>>(wx, wy, wz);
    gaunt_main_kernel<<<NBATCH, 128>>>(x, y, out);
}

// round 9
// speedup vs baseline: 1.6490x; 1.2795x over previous
#include <cuda_runtime.h>
#include <utility>

#define RB 20
#define RA 19
#define MUL 128
#define NC 128
#define NBATCH 1024
#define D1 9
#define DZ 25
#define ZSTRIDE 28     // padded z row stride (112B, 16B aligned)
#define ZROW (NC * ZSTRIDE)          // 3584 floats per node in scratch
#define XYSTRIDE 20    // [xd1..8][yd1..8][xd0][yd0][pad2] (80B, 16B aligned)

// ===================== compile-time selection rules =====================
__host__ __device__ constexpr int lof(int d) {
    return (d < 1) ? 0 : (d < 4) ? 1 : (d < 9) ? 2 : (d < 16) ? 3 : 4;
}
__host__ __device__ constexpr bool gaunt_nz(int i, int j, int d) {
    const int l1 = lof(i), m1 = i - l1 * l1 - l1;
    const int l2 = lof(j), m2 = j - l2 * l2 - l2;
    const int L  = lof(d), M  = d - L * L - L;
    if ((l1 + l2 + L) & 1) return false;
    const int lo = (l1 > l2) ? (l1 - l2) : (l2 - l1);
    if (L < lo || L > l1 + l2) return false;
    const int f1 = m1 < 0 ? -m1 : m1;
    const int f2 = m2 < 0 ? -m2 : m2;
    const int F  = M  < 0 ? -M  : M;
    const int fd = (f1 > f2) ? (f1 - f2) : (f2 - f1);
    if (!(F == f1 + f2 || F == fd)) return false;
    if (((m1 < 0) + (m2 < 0) + (M < 0)) & 1) return false;
    return true;
}

// ===================== compile-time Gaunt table =====================
namespace cgaunt {

constexpr double PI = 3.14159265358979323846;

constexpr double csqrt(double x) {
    double r = (x > 1.0) ? x : 1.0;
    for (int i = 0; i < 80; ++i) r = 0.5 * (r + x / r);
    return r;
}
constexpr double redang(double x) {
    while (x >  PI) x -= 2.0 * PI;
    while (x < -PI) x += 2.0 * PI;
    return x;
}
constexpr double ccos(double x) {
    x = redang(x);
    double x2 = x * x, t = 1.0, s = 1.0;
    for (int k = 1; k <= 22; ++k) { t *= -x2 / ((2.0 * k - 1.0) * (2.0 * k)); s += t; }
    return s;
}
constexpr double csin(double x) {
    x = redang(x);
    double x2 = x * x, t = x, s = x;
    for (int k = 1; k <= 22; ++k) { t *= -x2 / ((2.0 * k) * (2.0 * k + 1.0)); s += t; }
    return s;
}
constexpr double cfact(int k) { double f = 1.0; for (int v = 2; v <= k; ++v) f *= v; return f; }

constexpr double alegP(int l, int m, double x) {
    double pmm = 1.0;
    if (m > 0) {
        double df = 1.0;
        for (int k = 1; k < 2 * m; k += 2) df *= (double)k;
        double somx2 = csqrt(1.0 - x * x);
        double s = 1.0;
        for (int k = 0; k < m; ++k) s *= somx2;
        pmm = ((m & 1) ? -1.0 : 1.0) * df * s;
    }
    if (l == m) return pmm;
    double pmmp1 = x * (2.0 * m + 1.0) * pmm;
    if (l == m + 1) return pmmp1;
    for (int ll = m + 2; ll <= l; ++ll) {
        double p = ((2.0 * ll - 1.0) * x * pmmp1 - (ll + m - 1.0) * pmm) / (double)(ll - m);
        pmm = pmmp1; pmmp1 = p;
    }
    return pmmp1;
}

struct GTab { double g[81][DZ]; };

constexpr GTab make_gaunt() {
    GTab T{};
    double ct[RB] = {}, qw[RB] = {};
    for (int i = 0; i < RB; ++i) {
        double xv = ccos(PI * (i + 0.75) / (RB + 0.5));
        double dp = 0.0;
        for (int it = 0; it < 60; ++it) {
            double p0 = 1.0, p1 = xv;
            for (int k = 2; k <= RB; ++k) {
                double p = ((2.0 * k - 1.0) * xv * p1 - (k - 1.0) * p0) / (double)k;
                p0 = p1; p1 = p;
            }
            dp = RB * (xv * p1 - p0) / (xv * xv - 1.0);
            xv -= p1 / dp;
        }
        {
            double p0 = 1.0, p1 = xv;
            for (int k = 2; k <= RB; ++k) {
                double p = ((2.0 * k - 1.0) * xv * p1 - (k - 1.0) * p0) / (double)k;
                p0 = p1; p1 = p;
            }
            dp = RB * (xv * p1 - p0) / (xv * xv - 1.0);
        }
        ct[i] = xv;
        qw[i] = 2.0 / ((1.0 - xv * xv) * dp * dp);
    }
    double Pn[DZ][RB] = {}, U[DZ][RA] = {};
    for (int d = 0; d < DZ; ++d) {
        int l = lof(d);
        int m = d - l * l - l;
        int am = m < 0 ? -m : m;
        double nlm = csqrt((2.0 * l + 1.0) / (4.0 * PI) * cfact(l - am) / cfact(l + am));
        for (int b = 0; b < RB; ++b) Pn[d][b] = nlm * alegP(l, am, ct[b]);
        for (int a = 0; a < RA; ++a) {
            double al = 2.0 * PI * (double)a / (double)RA;
            U[d][a] = (m == 0) ? 1.0
                    : (m > 0 ? csqrt(2.0) * ccos((double)m * al)
                             : csqrt(2.0) * csin((double)am * al));
        }
    }
    const double scale = (2.0 * PI / (double)RA) / (double)MUL / csqrt((double)NC);
    for (int i = 0; i < 9; ++i)
        for (int j = 0; j < 9; ++j)
            for (int d = 0; d < DZ; ++d) {
                if (!gaunt_nz(i, j, d)) { T.g[i * 9 + j][d] = 0.0; continue; }
                double angs = 0.0;
                for (int a = 0; a < RA; ++a) angs += U[i][a] * U[j][a] * U[d][a];
                double bets = 0.0;
                for (int b = 0; b < RB; ++b) bets += qw[b] * Pn[i][b] * Pn[j][b] * Pn[d][b];
                T.g[i * 9 + j][d] = angs * bets * scale;
            }
    return T;
}

constexpr GTab GG = make_gaunt();

} // namespace cgaunt

// ===================== static_for =====================
template <typename F, int... Is>
__device__ __forceinline__ void sfor_impl(F&& f, std::integer_sequence<int, Is...>) {
    (f(std::integral_constant<int, Is>{}), ...);
}
template <int N, typename F>
__device__ __forceinline__ void sfor(F&& f) {
    sfor_impl(static_cast<F&&>(f), std::make_integer_sequence<int, N>{});
}

// ===================== packed f32x2 helpers =====================
__device__ __forceinline__ unsigned long long pk2(float lo, float hi) {
    unsigned long long r;
    asm("mov.b64 %0, {%1, %2};" : "=l"(r) : "f"(lo), "f"(hi));
    return r;
}
__device__ __forceinline__ void ffma2(unsigned long long& d,
                                      unsigned long long a, unsigned long long b) {
    asm("fma.rn.f32x2 %0, %1, %2, %0;" : "+l"(d) : "l"(a), "l"(b));
}
__device__ __forceinline__ void unpk2(unsigned long long v, float& lo, float& hi) {
    asm("mov.b64 {%0, %1}, %2;" : "=f"(lo), "=f"(hi) : "l"(v));
}

// ===================== device scratch =====================
__device__ float4 WA[MUL * NC];    // (wx_l0, wx_l1, wx_l2, wy_l0) at [m*128+c]
__device__ float2 WB[MUL * NC];    // (wy_l1, wy_l2)
__device__ float4 WZ4[NC * NC];    // (wz_l0..wz_l3) at [cc*128+c]
__device__ float  WZ1[NC * NC];    // wz_l4
__device__ float  ZS[NBATCH * ZROW];   // 14.7 MB z scratch (padded rows)

__global__ void pack_weights(const float* __restrict__ wx,
                             const float* __restrict__ wy,
                             const float* __restrict__ wz) {
    int idx = blockIdx.x * 256 + threadIdx.x;   // 0..16383
    WA[idx] = make_float4(wx[idx], wx[16384 + idx], wx[32768 + idx], wy[idx]);
    WB[idx] = make_float2(wy[16384 + idx], wy[32768 + idx]);
    WZ4[idx] = make_float4(wz[idx], wz[16384 + idx], wz[32768 + idx], wz[49152 + idx]);
    WZ1[idx] = wz[65536 + idx];
}

// ===================== sparse Gaunt contraction (compile-time coeffs) ========
__device__ __forceinline__ void gaunt_contract_ct(const float* __restrict__ xc,
                                                  const float* __restrict__ yc,
                                                  float* __restrict__ z) {
    #pragma unroll
    for (int d = 0; d < DZ; ++d) z[d] = 0.0f;
    sfor<9>([&](auto I) {
        constexpr int i = decltype(I)::value;
        sfor<9>([&](auto J) {
            constexpr int j = decltype(J)::value;
            float p = xc[i] * yc[j];
            sfor<DZ>([&](auto Dd) {
                constexpr int d = decltype(Dd)::value;
                if constexpr (gaunt_nz(i, j, d)) {
                    constexpr float gv = (float)cgaunt::GG.g[i * 9 + j][d];
                    z[d] = fmaf(p, gv, z[d]);
                }
            });
        });
    });
}

// ===================== K1: linear-in + Gaunt -> z scratch =====================
__global__ void __launch_bounds__(128, 9)
k1_linear_gaunt(const float* __restrict__ x, const float* __restrict__ y) {
    __shared__ __align__(16) float pool[ZROW];   // 14336 B

    const int c = threadIdx.x;
    const int n = blockIdx.x;

    // ---- stage-in: xy row m = [xd1..8][yd1..8][xd0][yd0][pad2] ----
    {
        const float* xg = x + (size_t)n * MUL * D1;
        const float* yg = y + (size_t)n * MUL * D1;
        #pragma unroll
        for (int it = 0; it < 9; ++it) {
            int idx = c + it * 128;
            int m = idx / 9, dd = idx - m * 9;
            int kx = (dd == 0) ? 16 : (dd - 1);
            int ky = (dd == 0) ? 17 : (7 + dd);
            pool[m * XYSTRIDE + kx] = xg[idx];
            pool[m * XYSTRIDE + ky] = yg[idx];
        }
    }
    __syncthreads();

    // ---- stage 1: per-l linear in (packed f32x2, pre-packed weights) ----
    unsigned long long Ax[4], Ay[4];
    float sx = 0.0f, sy = 0.0f;
    #pragma unroll
    for (int k = 0; k < 4; ++k) { Ax[k] = Ay[k] = 0ULL; }

    #pragma unroll 4
    for (int m = 0; m < MUL; ++m) {
        float4 wa = WA[m * NC + c];
        float2 wb = WB[m * NC + c];
        const float* row = &pool[m * XYSTRIDE];
        float4 xv0 = *(const float4*)(row);       // xd1..xd4
        float4 xv1 = *(const float4*)(row + 4);   // xd5..xd8
        float4 yv0 = *(const float4*)(row + 8);   // yd1..yd4
        float4 yv1 = *(const float4*)(row + 12);  // yd5..yd8
        float2 d0  = *(const float2*)(row + 16);  // xd0, yd0
        ffma2(Ax[0], pk2(xv0.x, xv0.y), pk2(wa.y, wa.y));
        ffma2(Ax[1], pk2(xv0.z, xv0.w), pk2(wa.y, wa.z));
        ffma2(Ax[2], pk2(xv1.x, xv1.y), pk2(wa.z, wa.z));
        ffma2(Ax[3], pk2(xv1.z, xv1.w), pk2(wa.z, wa.z));
        sx += d0.x * wa.x;
        ffma2(Ay[0], pk2(yv0.x, yv0.y), pk2(wb.x, wb.x));
        ffma2(Ay[1], pk2(yv0.z, yv0.w), pk2(wb.x, wb.y));
        ffma2(Ay[2], pk2(yv1.x, yv1.y), pk2(wb.y, wb.y));
        ffma2(Ay[3], pk2(yv1.z, yv1.w), pk2(wb.y, wb.y));
        sy += d0.y * wa.w;
    }

    float xc[9], yc[9];
    xc[0] = sx; yc[0] = sy;
    #pragma unroll
    for (int k = 0; k < 4; ++k) {
        unpk2(Ax[k], xc[2 * k + 1], xc[2 * k + 2]);
        unpk2(Ay[k], yc[2 * k + 1], yc[2 * k + 2]);
    }

    // ---- stage 2: sparse Gaunt contraction (registers + immediates only) ----
    float z[DZ];
    gaunt_contract_ct(xc, yc, z);

    __syncthreads();   // all warps done reading xy before z overwrites pool

    // ---- z -> smem padded rows, then coalesced float4 copy to scratch ----
    {
        float* zr = &pool[c * ZSTRIDE];  // 112B stride -> 16B aligned
        *(float4*)(zr)      = make_float4(z[0],  z[1],  z[2],  z[3]);
        *(float4*)(zr + 4)  = make_float4(z[4],  z[5],  z[6],  z[7]);
        *(float4*)(zr + 8)  = make_float4(z[8],  z[9],  z[10], z[11]);
        *(float4*)(zr + 12) = make_float4(z[12], z[13], z[14], z[15]);
        *(float4*)(zr + 16) = make_float4(z[16], z[17], z[18], z[19]);
        *(float4*)(zr + 20) = make_float4(z[20], z[21], z[22], z[23]);
        zr[24] = z[24];
    }
    __syncthreads();

    float4* zg4 = (float4*)(ZS + (size_t)n * ZROW);     // n*14336B, 16B aligned
    const float4* p4 = (const float4*)pool;
    #pragma unroll
    for (int it = 0; it < 7; ++it) {                     // 7*128 = 896 = ZROW/4
        zg4[it * 128 + c] = p4[it * 128 + c];
    }
}

// ===================== K2: channel mixing =====================
__global__ void __launch_bounds__(128, 7)
k2_mix(float* __restrict__ out) {
    __shared__ __align__(16) float zs[ZROW];   // 14336 B

    const int c = threadIdx.x;
    const int n = blockIdx.x;

    // ---- stage z in: straight float4 copy (padded layout preserved) ----
    {
        const float4* zg4 = (const float4*)(ZS + (size_t)n * ZROW);
        float4* s4 = (float4*)zs;
        #pragma unroll
        for (int it = 0; it < 7; ++it) {
            s4[it * 128 + c] = zg4[it * 128 + c];
        }
    }
    __syncthreads();

    // ---- per-l channel mixing, packed f32x2 ----
    unsigned long long a[12];
    float as = 0.0f;
    #pragma unroll
    for (int k = 0; k < 12; ++k) a[k] = 0ULL;

    #pragma unroll 2
    for (int cc = 0; cc < NC; ++cc) {
        float4 wv = WZ4[cc * NC + c];
        float  w4 = WZ1[cc * NC + c];
        const float* zp = &zs[cc * ZSTRIDE];
        float4 q0 = *(const float4*)(zp);
        float4 q1 = *(const float4*)(zp + 4);
        float4 q2 = *(const float4*)(zp + 8);
        float4 q3 = *(const float4*)(zp + 12);
        float4 q4 = *(const float4*)(zp + 16);
        float4 q5 = *(const float4*)(zp + 20);
        float  zl = zp[24];
        ffma2(a[0],  pk2(q0.x, q0.y), pk2(wv.x, wv.y));
        ffma2(a[1],  pk2(q0.z, q0.w), pk2(wv.y, wv.y));
        ffma2(a[2],  pk2(q1.x, q1.y), pk2(wv.z, wv.z));
        ffma2(a[3],  pk2(q1.z, q1.w), pk2(wv.z, wv.z));
        ffma2(a[4],  pk2(q2.x, q2.y), pk2(wv.z, wv.w));
        ffma2(a[5],  pk2(q2.z, q2.w), pk2(wv.w, wv.w));
        ffma2(a[6],  pk2(q3.x, q3.y), pk2(wv.w, wv.w));
        ffma2(a[7],  pk2(q3.z, q3.w), pk2(wv.w, wv.w));
        ffma2(a[8],  pk2(q4.x, q4.y), pk2(w4, w4));
        ffma2(a[9],  pk2(q4.z, q4.w), pk2(w4, w4));
        ffma2(a[10], pk2(q5.x, q5.y), pk2(w4, w4));
        ffma2(a[11], pk2(q5.z, q5.w), pk2(w4, w4));
        as += zl * w4;
    }
    __syncthreads();   // everyone done reading zs before epilogue overwrites it

    // ---- epilogue: accums -> smem unpadded (stride 25: conflict-free), ----
    // ---- then fully coalesced copy to out                               ----
    {
        float* r = &zs[c * DZ];
        #pragma unroll
        for (int k = 0; k < 12; ++k) {
            float lo, hi;
            unpk2(a[k], lo, hi);
            r[2 * k] = lo;
            r[2 * k + 1] = hi;
        }
        r[24] = as;
    }
    __syncthreads();

    float* og = out + (size_t)n * (NC * DZ);            // n*12800B: 16B aligned
    float4* og4 = (float4*)og;
    const float4* s4 = (const float4*)zs;
    #pragma unroll
    for (int it = 0; it < 6; ++it) {                     // 6*128*4 = 3072 floats
        og4[it * 128 + c] = s4[it * 128 + c];
    }
    og[3072 + c] = zs[3072 + c];                         // tail 128 floats
}

extern "C" void kernel_launch(void* const* d_in, const int* in_sizes, int n_in,
                              void* d_out, int out_size) {
    const float* x  = (const float*)d_in[0];
    const float* y  = (const float*)d_in[1];
    const float* wx = (const float*)d_in[2];
    const float* wy = (const float*)d_in[3];
    const float* wz = (const float*)d_in[4];
    float* out = (float*)d_out;

    pack_weights<<<64, 256>>>(wx, wy, wz);
    k1_linear_gaunt<<<NBATCH, 128>>>(x, y);
    k2_mix<<<NBATCH, 128>>>(out);
}